// round 1
// baseline (speedup 1.0000x reference)
#include <cuda_runtime.h>

#define BATCH  4
#define CCH    64          // input channels
#define NPIX   16384       // 128*128
#define NHEADS 8
#define DHEAD  64
#define INNER  512
#define EPSN   1e-12f

// ---------------- scratch (device globals; no allocation allowed) -------------
__device__ float g_G[BATCH * CCH * CCH];   // per-batch Gram  X^T X   [4][64][64]
__device__ float g_P[BATCH * CCH * CCH];   // per-batch fused proj    [4][64][64]

// ---------------- K0: zero scratch -------------------------------------------
__global__ void zero_kernel() {
    int i = blockIdx.x * blockDim.x + threadIdx.x;
    if (i < BATCH * CCH * CCH) { g_G[i] = 0.f; g_P[i] = 0.f; }
}

// ---------------- K1: Gram  G_b = X_b^T X_b ----------------------------------
// x layout: [b][c][n] (n contiguous). Block = (b, 256-pixel chunk).
#define NCHUNK 256
#define XS     257                       // padded row stride (odd -> conflict-free)
#define GRAM_SMEM (CCH * XS * 4)

__global__ void gram_kernel(const float* __restrict__ x) {
    extern __shared__ float xs[];        // [64][257]
    const int b     = blockIdx.x >> 6;
    const int chunk = blockIdx.x & 63;
    const int n0    = chunk * NCHUNK;
    const int tid   = threadIdx.x;

    const float* xb = x + (size_t)b * CCH * NPIX + n0;
    #pragma unroll 4
    for (int c = 0; c < CCH; c++)
        xs[c * XS + tid] = xb[(size_t)c * NPIX + tid];
    __syncthreads();

    // 256 threads, strided 4x4 register tile over 64x64 outputs.
    const int ti = tid >> 4;             // 0..15  -> rows ti + 16u
    const int tj = tid & 15;             // 0..15  -> cols tj + 16v
    float acc[4][4];
    #pragma unroll
    for (int u = 0; u < 4; u++)
        #pragma unroll
        for (int v = 0; v < 4; v++) acc[u][v] = 0.f;

    for (int n = 0; n < NCHUNK; n++) {
        float a[4], bb[4];
        #pragma unroll
        for (int u = 0; u < 4; u++) a[u]  = xs[(ti + 16 * u) * XS + n];
        #pragma unroll
        for (int v = 0; v < 4; v++) bb[v] = xs[(tj + 16 * v) * XS + n];
        #pragma unroll
        for (int u = 0; u < 4; u++)
            #pragma unroll
            for (int v = 0; v < 4; v++) acc[u][v] = fmaf(a[u], bb[v], acc[u][v]);
    }

    float* Gb = g_G + b * CCH * CCH;
    #pragma unroll
    for (int u = 0; u < 4; u++)
        #pragma unroll
        for (int v = 0; v < 4; v++)
            atomicAdd(&Gb[(ti + 16 * u) * CCH + (tj + 16 * v)], acc[u][v]);
}

// ---------------- K2: per-(b,h) attention in channel space -------------------
// attn_raw = Wk_h^T G Wq_h ; norms from diag quadratic forms; softmax;
// M = attn^T-fold with Wp_h ; P_b += Wv_h @ M_h   (atomic over heads)
#define S65 65
#define ATTN_SMEM ((CCH * S65 /*G*/ + CCH * CCH /*W*/ + CCH * S65 /*T*/ + \
                    CCH * S65 /*R*/ + 2 * CCH /*qn,kn*/) * 4)

__global__ void attn_kernel(const float* __restrict__ Wq,
                            const float* __restrict__ Wk,
                            const float* __restrict__ Wv,
                            const float* __restrict__ Wp,
                            const float* __restrict__ rescale,
                            float* __restrict__ attn_out) {
    extern __shared__ float sm[];
    float* Gs = sm;                        // 64*65 (also reused for Wp)
    float* Ws = Gs + CCH * S65;            // 64*64
    float* Ts = Ws + CCH * CCH;            // 64*65
    float* Rs = Ts + CCH * S65;            // 64*65
    float* qn = Rs + CCH * S65;            // 64
    float* kn = qn + CCH;                  // 64

    const int b   = blockIdx.x >> 3;
    const int h   = blockIdx.x & 7;
    const int tid = threadIdx.x;
    const int e   = tid & 63;
    const int rb  = (tid >> 6) * 16;

    // load G and Wq
    for (int i = tid; i < CCH * CCH; i += 256)
        Gs[(i >> 6) * S65 + (i & 63)] = g_G[b * CCH * CCH + i];
    for (int i = tid; i < CCH * CCH; i += 256)
        Ws[i] = Wq[(i >> 6) * INNER + h * DHEAD + (i & 63)];
    __syncthreads();

    // T1 = G @ Wq_h
    for (int r = rb; r < rb + 16; r++) {
        float acc = 0.f;
        #pragma unroll 8
        for (int c = 0; c < CCH; c++) acc = fmaf(Gs[r * S65 + c], Ws[c * CCH + e], acc);
        Ts[r * S65 + e] = acc;
    }
    __syncthreads();

    // qn[e] = diag(Wq^T T1)
    if (tid < CCH) {
        float s = 0.f;
        #pragma unroll 8
        for (int c = 0; c < CCH; c++) s = fmaf(Ws[c * CCH + tid], Ts[c * S65 + tid], s);
        qn[tid] = s;
    }
    __syncthreads();

    // load Wk (overwrite Wq)
    for (int i = tid; i < CCH * CCH; i += 256)
        Ws[i] = Wk[(i >> 6) * INNER + h * DHEAD + (i & 63)];
    __syncthreads();

    // attn_raw[d][e] = sum_c Wk[c][d] * T1[c][e]
    for (int d = rb; d < rb + 16; d++) {
        float acc = 0.f;
        #pragma unroll 8
        for (int c = 0; c < CCH; c++) acc = fmaf(Ws[c * CCH + d], Ts[c * S65 + e], acc);
        Rs[d * S65 + e] = acc;
    }
    __syncthreads();

    // T2 = G @ Wk_h (overwrite T1)
    for (int r = rb; r < rb + 16; r++) {
        float acc = 0.f;
        #pragma unroll 8
        for (int c = 0; c < CCH; c++) acc = fmaf(Gs[r * S65 + c], Ws[c * CCH + e], acc);
        Ts[r * S65 + e] = acc;
    }
    __syncthreads();

    if (tid < CCH) {
        float s = 0.f;
        #pragma unroll 8
        for (int c = 0; c < CCH; c++) s = fmaf(Ws[c * CCH + tid], Ts[c * S65 + tid], s);
        kn[tid] = s;
    }
    __syncthreads();

    // logits
    const float resc = rescale[h];
    for (int i = tid; i < CCH * CCH; i += 256) {
        int d = i >> 6, ee = i & 63;
        float inv = resc / (fmaxf(sqrtf(kn[d]), EPSN) * fmaxf(sqrtf(qn[ee]), EPSN));
        Rs[d * S65 + ee] *= inv;
    }
    __syncthreads();

    // softmax over e (row d)
    if (tid < CCH) {
        float m = -1e30f;
        for (int ee = 0; ee < CCH; ee++) m = fmaxf(m, Rs[tid * S65 + ee]);
        float s = 0.f;
        for (int ee = 0; ee < CCH; ee++) {
            float v = __expf(Rs[tid * S65 + ee] - m);
            Rs[tid * S65 + ee] = v;
            s += v;
        }
        float invs = 1.f / s;
        for (int ee = 0; ee < CCH; ee++) Rs[tid * S65 + ee] *= invs;
    }
    __syncthreads();

    // write attn output [b][h][d][e]
    float* ao = attn_out + (size_t)(b * NHEADS + h) * DHEAD * DHEAD;
    for (int i = tid; i < CCH * CCH; i += 256)
        ao[i] = Rs[(i >> 6) * S65 + (i & 63)];

    // load Wp_h into Gs (contiguous rows h*64..h*64+63), Wv_h into Ws
    for (int i = tid; i < CCH * CCH; i += 256)
        Gs[i] = Wp[h * DHEAD * CCH + i];                 // [d][c]
    for (int i = tid; i < CCH * CCH; i += 256)
        Ws[i] = Wv[(i >> 6) * INNER + h * DHEAD + (i & 63)];  // [cin][e]
    __syncthreads();

    // M[e][c] = sum_d attn[d][e] * Wp[d][c]   (into Ts, stride 65)
    {
        const int c = tid & 63;
        for (int ee2 = rb; ee2 < rb + 16; ee2++) {
            float acc = 0.f;
            #pragma unroll 8
            for (int d = 0; d < CCH; d++) acc = fmaf(Rs[d * S65 + ee2], Gs[d * CCH + c], acc);
            Ts[ee2 * S65 + c] = acc;
        }
    }
    __syncthreads();

    // P_b[cin][c] += sum_e Wv[cin][e] * M[e][c]
    {
        const int c = tid & 63;
        float* Pb = g_P + b * CCH * CCH;
        for (int cin = rb; cin < rb + 16; cin++) {
            float acc = 0.f;
            #pragma unroll 8
            for (int ee2 = 0; ee2 < CCH; ee2++) acc = fmaf(Ws[cin * CCH + ee2], Ts[ee2 * S65 + c], acc);
            atomicAdd(&Pb[cin * CCH + c], acc);
        }
    }
}

// ---------------- K3: out = X @ P + bp, written as [b][c][n] -----------------
#define ONTILE 128
#define X2S    132                         // padded (16B-aligned) row stride
#define OUT_SMEM ((CCH * X2S + CCH * CCH + CCH) * 4)

__global__ void out_kernel(const float* __restrict__ x,
                           const float* __restrict__ bp,
                           float* __restrict__ out) {
    extern __shared__ float sm[];
    float* xs  = sm;                       // [64][132]
    float* Ps  = xs + CCH * X2S;           // [64][64]
    float* bps = Ps + CCH * CCH;           // [64]

    const int b     = blockIdx.x >> 7;
    const int chunk = blockIdx.x & 127;
    const int n0    = chunk * ONTILE;
    const int tid   = threadIdx.x;

    for (int i = tid; i < CCH * CCH; i += 256) Ps[i] = g_P[b * CCH * CCH + i];
    if (tid < CCH) bps[tid] = bp[tid];

    const float* xb = x + (size_t)b * CCH * NPIX + n0;
    for (int idx = tid; idx < CCH * (ONTILE / 4); idx += 256) {
        int row = idx >> 5, q4 = idx & 31;
        float4 v = *(const float4*)(xb + (size_t)row * NPIX + q4 * 4);
        *(float4*)(xs + row * X2S + q4 * 4) = v;
    }
    __syncthreads();

    const int tx = tid & 31;               // n: tx*4 .. tx*4+3
    const int ty = tid >> 5;               // c: ty*8 .. ty*8+7
    const int c0 = ty * 8;

    float acc[8][4];
    #pragma unroll
    for (int u = 0; u < 8; u++)
        #pragma unroll
        for (int v = 0; v < 4; v++) acc[u][v] = 0.f;

    for (int j = 0; j < CCH; j++) {
        float4 xv = *(const float4*)(xs + j * X2S + tx * 4);
        float4 p0 = *(const float4*)(Ps + j * CCH + c0);
        float4 p1 = *(const float4*)(Ps + j * CCH + c0 + 4);
        float pr[8] = {p0.x, p0.y, p0.z, p0.w, p1.x, p1.y, p1.z, p1.w};
        float xr[4] = {xv.x, xv.y, xv.z, xv.w};
        #pragma unroll
        for (int u = 0; u < 8; u++)
            #pragma unroll
            for (int v = 0; v < 4; v++) acc[u][v] = fmaf(pr[u], xr[v], acc[u][v]);
    }

    #pragma unroll
    for (int u = 0; u < 8; u++) {
        float bias = bps[c0 + u];
        float4 o;
        o.x = acc[u][0] + bias; o.y = acc[u][1] + bias;
        o.z = acc[u][2] + bias; o.w = acc[u][3] + bias;
        *(float4*)(out + ((size_t)(b * CCH + c0 + u)) * NPIX + n0 + tx * 4) = o;
    }
}

// ---------------- launch ------------------------------------------------------
extern "C" void kernel_launch(void* const* d_in, const int* in_sizes, int n_in,
                              void* d_out, int out_size) {
    const float* x       = (const float*)d_in[0];
    const float* Wq      = (const float*)d_in[1];
    const float* Wk      = (const float*)d_in[2];
    const float* Wv      = (const float*)d_in[3];
    const float* Wp      = (const float*)d_in[4];
    const float* bp      = (const float*)d_in[5];
    const float* rescale = (const float*)d_in[6];

    float* out      = (float*)d_out;
    float* attn_out = out + (size_t)out_size - (size_t)BATCH * NHEADS * DHEAD * DHEAD;

    cudaFuncSetAttribute(gram_kernel, cudaFuncAttributeMaxDynamicSharedMemorySize, GRAM_SMEM);
    cudaFuncSetAttribute(attn_kernel, cudaFuncAttributeMaxDynamicSharedMemorySize, ATTN_SMEM);
    cudaFuncSetAttribute(out_kernel,  cudaFuncAttributeMaxDynamicSharedMemorySize, OUT_SMEM);

    zero_kernel<<<(BATCH * CCH * CCH + 255) / 256, 256>>>();
    gram_kernel<<<BATCH * 64, 256, GRAM_SMEM>>>(x);
    attn_kernel<<<BATCH * NHEADS, 256, ATTN_SMEM>>>(Wq, Wk, Wv, Wp, rescale, attn_out);
    out_kernel<<<BATCH * (NPIX / ONTILE), 256, OUT_SMEM>>>(x, bp, out);
}

// round 2
// speedup vs baseline: 1.7090x; 1.7090x over previous
#include <cuda_runtime.h>

#define BATCH  4
#define CCH    64
#define NPIX   16384
#define NHEADS 8
#define DHEAD  64
#define INNER  512
#define EPSN   1e-12f

// ---------------- scratch ------------------------------------------------------
__device__ float g_G[BATCH * CCH * CCH];
__device__ float g_P[BATCH * CCH * CCH];

__global__ void zero_kernel() {
    int i = blockIdx.x * blockDim.x + threadIdx.x;
    if (i < BATCH * CCH * CCH) { g_G[i] = 0.f; g_P[i] = 0.f; }
}

// ---------------- K1: Gram (upper triangle only, mirrored) --------------------
#define NCHUNK 256
#define XS     257
#define GRAM_THREADS 160
#define GRAM_SMEM (CCH * XS * 4)

__global__ void __launch_bounds__(GRAM_THREADS)
gram_kernel(const float* __restrict__ x) {
    extern __shared__ float xs[];             // [64][257]
    const int b     = blockIdx.x >> 6;
    const int chunk = blockIdx.x & 63;
    const int n0    = chunk * NCHUNK;
    const int tid   = threadIdx.x;

    const float* xb = x + (size_t)b * CCH * NPIX + n0;
    for (int i = tid; i < CCH * NCHUNK; i += GRAM_THREADS) {
        int c = i >> 8, n = i & 255;
        xs[c * XS + n] = xb[(size_t)c * NPIX + n];
    }
    __syncthreads();

    if (tid < 136) {
        // decode upper-triangular 4x4 tile (i <= j) on 16x16 tile grid
        int i = 0, base = 0;
        while (base + (16 - i) <= tid) { base += 16 - i; i++; }
        int j = i + (tid - base);

        const float* ra = xs + (i * 4) * XS;
        const float* rb = xs + (j * 4) * XS;

        float acc[4][4];
        #pragma unroll
        for (int u = 0; u < 4; u++)
            #pragma unroll
            for (int v = 0; v < 4; v++) acc[u][v] = 0.f;

        #pragma unroll 2
        for (int n = 0; n < NCHUNK; n++) {
            float a0 = ra[n], a1 = ra[XS + n], a2 = ra[2 * XS + n], a3 = ra[3 * XS + n];
            float b0 = rb[n], b1 = rb[XS + n], b2 = rb[2 * XS + n], b3 = rb[3 * XS + n];
            acc[0][0] = fmaf(a0, b0, acc[0][0]); acc[0][1] = fmaf(a0, b1, acc[0][1]);
            acc[0][2] = fmaf(a0, b2, acc[0][2]); acc[0][3] = fmaf(a0, b3, acc[0][3]);
            acc[1][0] = fmaf(a1, b0, acc[1][0]); acc[1][1] = fmaf(a1, b1, acc[1][1]);
            acc[1][2] = fmaf(a1, b2, acc[1][2]); acc[1][3] = fmaf(a1, b3, acc[1][3]);
            acc[2][0] = fmaf(a2, b0, acc[2][0]); acc[2][1] = fmaf(a2, b1, acc[2][1]);
            acc[2][2] = fmaf(a2, b2, acc[2][2]); acc[2][3] = fmaf(a2, b3, acc[2][3]);
            acc[3][0] = fmaf(a3, b0, acc[3][0]); acc[3][1] = fmaf(a3, b1, acc[3][1]);
            acc[3][2] = fmaf(a3, b2, acc[3][2]); acc[3][3] = fmaf(a3, b3, acc[3][3]);
        }

        float* Gb = g_G + b * CCH * CCH;
        const int r4 = i * 4, c4 = j * 4;
        #pragma unroll
        for (int u = 0; u < 4; u++)
            #pragma unroll
            for (int v = 0; v < 4; v++)
                atomicAdd(&Gb[(r4 + u) * CCH + (c4 + v)], acc[u][v]);
        if (i != j) {
            #pragma unroll
            for (int u = 0; u < 4; u++)
                #pragma unroll
                for (int v = 0; v < 4; v++)
                    atomicAdd(&Gb[(c4 + v) * CCH + (r4 + u)], acc[u][v]);
        }
    }
}

// ---------------- K2: attention in channel space ------------------------------
// smem floats: Gs 64*65 | Wq 64*64 | Wk 64*64 | T1 64*68 | T2 64*68 | A 64*68 |
//              Wp 64*64 | WvT 64*68 | qn 64 | kn 64
#define S68 68
#define OFF_G    0
#define OFF_WQ   (OFF_G  + CCH * 65)
#define OFF_WK   (OFF_WQ + CCH * CCH)
#define OFF_T1   (OFF_WK + CCH * CCH)
#define OFF_T2   (OFF_T1 + CCH * S68)
#define OFF_A    (OFF_T2 + CCH * S68)
#define OFF_WP   (OFF_A  + CCH * S68)
#define OFF_WVT  (OFF_WP + CCH * CCH)
#define OFF_QN   (OFF_WVT + CCH * S68)
#define OFF_KN   (OFF_QN + CCH)
#define ATTN_SMEM ((OFF_KN + CCH) * 4)

__global__ void __launch_bounds__(256)
attn_kernel(const float* __restrict__ Wq,
            const float* __restrict__ Wk,
            const float* __restrict__ Wv,
            const float* __restrict__ Wp,
            const float* __restrict__ rescale,
            float* __restrict__ attn_out) {
    extern __shared__ float sm[];
    float* Gs  = sm + OFF_G;
    float* Wqs = sm + OFF_WQ;
    float* Wks = sm + OFF_WK;
    float* T1  = sm + OFF_T1;
    float* T2  = sm + OFF_T2;
    float* As  = sm + OFF_A;
    float* Wps = sm + OFF_WP;
    float* WvT = sm + OFF_WVT;
    float* qn  = sm + OFF_QN;
    float* kn  = sm + OFF_KN;

    const int b   = blockIdx.x >> 3;
    const int h   = blockIdx.x & 7;
    const int tid = threadIdx.x;
    const int ti  = tid >> 4, tj = tid & 15;
    const int r0  = ti * 4,   e0 = tj * 4;

    for (int i = tid; i < CCH * CCH; i += 256) {
        int r = i >> 6, c = i & 63;
        Gs[r * 65 + c] = g_G[b * CCH * CCH + i];
        Wqs[i] = Wq[r * INNER + h * DHEAD + c];
        Wks[i] = Wk[r * INNER + h * DHEAD + c];
    }
    __syncthreads();

    // T1 = G @ Wq, T2 = G @ Wk (fused pass)
    {
        float aq[4][4], ak[4][4];
        #pragma unroll
        for (int u = 0; u < 4; u++)
            #pragma unroll
            for (int v = 0; v < 4; v++) { aq[u][v] = 0.f; ak[u][v] = 0.f; }

        for (int c = 0; c < CCH; c++) {
            float a0 = Gs[(r0 + 0) * 65 + c], a1 = Gs[(r0 + 1) * 65 + c];
            float a2 = Gs[(r0 + 2) * 65 + c], a3 = Gs[(r0 + 3) * 65 + c];
            float4 bq = *(const float4*)&Wqs[c * CCH + e0];
            float4 bk = *(const float4*)&Wks[c * CCH + e0];
            aq[0][0]=fmaf(a0,bq.x,aq[0][0]); aq[0][1]=fmaf(a0,bq.y,aq[0][1]); aq[0][2]=fmaf(a0,bq.z,aq[0][2]); aq[0][3]=fmaf(a0,bq.w,aq[0][3]);
            aq[1][0]=fmaf(a1,bq.x,aq[1][0]); aq[1][1]=fmaf(a1,bq.y,aq[1][1]); aq[1][2]=fmaf(a1,bq.z,aq[1][2]); aq[1][3]=fmaf(a1,bq.w,aq[1][3]);
            aq[2][0]=fmaf(a2,bq.x,aq[2][0]); aq[2][1]=fmaf(a2,bq.y,aq[2][1]); aq[2][2]=fmaf(a2,bq.z,aq[2][2]); aq[2][3]=fmaf(a2,bq.w,aq[2][3]);
            aq[3][0]=fmaf(a3,bq.x,aq[3][0]); aq[3][1]=fmaf(a3,bq.y,aq[3][1]); aq[3][2]=fmaf(a3,bq.z,aq[3][2]); aq[3][3]=fmaf(a3,bq.w,aq[3][3]);
            ak[0][0]=fmaf(a0,bk.x,ak[0][0]); ak[0][1]=fmaf(a0,bk.y,ak[0][1]); ak[0][2]=fmaf(a0,bk.z,ak[0][2]); ak[0][3]=fmaf(a0,bk.w,ak[0][3]);
            ak[1][0]=fmaf(a1,bk.x,ak[1][0]); ak[1][1]=fmaf(a1,bk.y,ak[1][1]); ak[1][2]=fmaf(a1,bk.z,ak[1][2]); ak[1][3]=fmaf(a1,bk.w,ak[1][3]);
            ak[2][0]=fmaf(a2,bk.x,ak[2][0]); ak[2][1]=fmaf(a2,bk.y,ak[2][1]); ak[2][2]=fmaf(a2,bk.z,ak[2][2]); ak[2][3]=fmaf(a2,bk.w,ak[2][3]);
            ak[3][0]=fmaf(a3,bk.x,ak[3][0]); ak[3][1]=fmaf(a3,bk.y,ak[3][1]); ak[3][2]=fmaf(a3,bk.z,ak[3][2]); ak[3][3]=fmaf(a3,bk.w,ak[3][3]);
        }
        #pragma unroll
        for (int u = 0; u < 4; u++) {
            *(float4*)&T1[(r0 + u) * S68 + e0] = make_float4(aq[u][0], aq[u][1], aq[u][2], aq[u][3]);
            *(float4*)&T2[(r0 + u) * S68 + e0] = make_float4(ak[u][0], ak[u][1], ak[u][2], ak[u][3]);
        }
    }
    __syncthreads();

    // qn/kn: inverse norms (folded rsqrt)
    if (tid < 128) {
        const int e = tid & 63;
        const float* W = (tid < 64) ? Wqs : Wks;
        const float* T = (tid < 64) ? T1  : T2;
        float s = 0.f;
        #pragma unroll 8
        for (int c = 0; c < CCH; c++) s = fmaf(W[c * CCH + e], T[c * S68 + e], s);
        float inv = 1.f / fmaxf(sqrtf(s), EPSN);
        ((tid < 64) ? qn : kn)[e] = inv;
    }

    // A_raw = T2^T @ Wq   (= Wk^T G Wq since G symmetric)
    {
        float acc[4][4];
        #pragma unroll
        for (int u = 0; u < 4; u++)
            #pragma unroll
            for (int v = 0; v < 4; v++) acc[u][v] = 0.f;
        for (int c = 0; c < CCH; c++) {
            float4 av = *(const float4*)&T2[c * S68 + r0];
            float4 bv = *(const float4*)&Wqs[c * CCH + e0];
            acc[0][0]=fmaf(av.x,bv.x,acc[0][0]); acc[0][1]=fmaf(av.x,bv.y,acc[0][1]); acc[0][2]=fmaf(av.x,bv.z,acc[0][2]); acc[0][3]=fmaf(av.x,bv.w,acc[0][3]);
            acc[1][0]=fmaf(av.y,bv.x,acc[1][0]); acc[1][1]=fmaf(av.y,bv.y,acc[1][1]); acc[1][2]=fmaf(av.y,bv.z,acc[1][2]); acc[1][3]=fmaf(av.y,bv.w,acc[1][3]);
            acc[2][0]=fmaf(av.z,bv.x,acc[2][0]); acc[2][1]=fmaf(av.z,bv.y,acc[2][1]); acc[2][2]=fmaf(av.z,bv.z,acc[2][2]); acc[2][3]=fmaf(av.z,bv.w,acc[2][3]);
            acc[3][0]=fmaf(av.w,bv.x,acc[3][0]); acc[3][1]=fmaf(av.w,bv.y,acc[3][1]); acc[3][2]=fmaf(av.w,bv.z,acc[3][2]); acc[3][3]=fmaf(av.w,bv.w,acc[3][3]);
        }
        #pragma unroll
        for (int u = 0; u < 4; u++)
            *(float4*)&As[(r0 + u) * S68 + e0] = make_float4(acc[u][0], acc[u][1], acc[u][2], acc[u][3]);
    }

    // load Wp_h ([d][c]) and Wv_h transposed ([e][cin]) while A settles
    for (int i = tid; i < CCH * CCH; i += 256) {
        int r = i >> 6, c = i & 63;
        Wps[i] = Wp[(h * DHEAD + r) * CCH + c];
        WvT[c * S68 + r] = Wv[r * INNER + h * DHEAD + c];
    }
    __syncthreads();

    // scaled softmax over rows of A (4 lanes per row)
    {
        const int d = tid >> 2, g = tid & 3;
        float* row = As + d * S68;
        const float sk = kn[d] * rescale[h];
        float vals[16];
        float mx = -1e30f;
        #pragma unroll
        for (int k = 0; k < 16; k++) {
            int e = g + 4 * k;
            float v = row[e] * sk * qn[e];
            vals[k] = v;
            mx = fmaxf(mx, v);
        }
        mx = fmaxf(mx, __shfl_xor_sync(0xffffffffu, mx, 1));
        mx = fmaxf(mx, __shfl_xor_sync(0xffffffffu, mx, 2));
        float s = 0.f;
        #pragma unroll
        for (int k = 0; k < 16; k++) { vals[k] = __expf(vals[k] - mx); s += vals[k]; }
        s += __shfl_xor_sync(0xffffffffu, s, 1);
        s += __shfl_xor_sync(0xffffffffu, s, 2);
        float inv = 1.f / s;
        #pragma unroll
        for (int k = 0; k < 16; k++) row[g + 4 * k] = vals[k] * inv;
    }
    __syncthreads();

    // write attn [b][h][d][e]
    float* ao = attn_out + (size_t)(b * NHEADS + h) * DHEAD * DHEAD;
    for (int i = tid; i < CCH * CCH; i += 256)
        ao[i] = As[(i >> 6) * S68 + (i & 63)];

    // M[e][c] = sum_d A[d][e] * Wp[d][c]   (into T1)
    {
        float acc[4][4];
        #pragma unroll
        for (int u = 0; u < 4; u++)
            #pragma unroll
            for (int v = 0; v < 4; v++) acc[u][v] = 0.f;
        for (int d = 0; d < CCH; d++) {
            float4 av = *(const float4*)&As[d * S68 + r0];
            float4 bv = *(const float4*)&Wps[d * CCH + e0];
            acc[0][0]=fmaf(av.x,bv.x,acc[0][0]); acc[0][1]=fmaf(av.x,bv.y,acc[0][1]); acc[0][2]=fmaf(av.x,bv.z,acc[0][2]); acc[0][3]=fmaf(av.x,bv.w,acc[0][3]);
            acc[1][0]=fmaf(av.y,bv.x,acc[1][0]); acc[1][1]=fmaf(av.y,bv.y,acc[1][1]); acc[1][2]=fmaf(av.y,bv.z,acc[1][2]); acc[1][3]=fmaf(av.y,bv.w,acc[1][3]);
            acc[2][0]=fmaf(av.z,bv.x,acc[2][0]); acc[2][1]=fmaf(av.z,bv.y,acc[2][1]); acc[2][2]=fmaf(av.z,bv.z,acc[2][2]); acc[2][3]=fmaf(av.z,bv.w,acc[2][3]);
            acc[3][0]=fmaf(av.w,bv.x,acc[3][0]); acc[3][1]=fmaf(av.w,bv.y,acc[3][1]); acc[3][2]=fmaf(av.w,bv.z,acc[3][2]); acc[3][3]=fmaf(av.w,bv.w,acc[3][3]);
        }
        #pragma unroll
        for (int u = 0; u < 4; u++)
            *(float4*)&T1[(r0 + u) * S68 + e0] = make_float4(acc[u][0], acc[u][1], acc[u][2], acc[u][3]);
    }
    __syncthreads();

    // P[cin][c] += sum_e Wv[cin][e] * M[e][c]
    {
        float acc[4][4];
        #pragma unroll
        for (int u = 0; u < 4; u++)
            #pragma unroll
            for (int v = 0; v < 4; v++) acc[u][v] = 0.f;
        for (int e = 0; e < CCH; e++) {
            float4 av = *(const float4*)&WvT[e * S68 + r0];
            float4 bv = *(const float4*)&T1[e * S68 + e0];
            acc[0][0]=fmaf(av.x,bv.x,acc[0][0]); acc[0][1]=fmaf(av.x,bv.y,acc[0][1]); acc[0][2]=fmaf(av.x,bv.z,acc[0][2]); acc[0][3]=fmaf(av.x,bv.w,acc[0][3]);
            acc[1][0]=fmaf(av.y,bv.x,acc[1][0]); acc[1][1]=fmaf(av.y,bv.y,acc[1][1]); acc[1][2]=fmaf(av.y,bv.z,acc[1][2]); acc[1][3]=fmaf(av.y,bv.w,acc[1][3]);
            acc[2][0]=fmaf(av.z,bv.x,acc[2][0]); acc[2][1]=fmaf(av.z,bv.y,acc[2][1]); acc[2][2]=fmaf(av.z,bv.z,acc[2][2]); acc[2][3]=fmaf(av.z,bv.w,acc[2][3]);
            acc[3][0]=fmaf(av.w,bv.x,acc[3][0]); acc[3][1]=fmaf(av.w,bv.y,acc[3][1]); acc[3][2]=fmaf(av.w,bv.z,acc[3][2]); acc[3][3]=fmaf(av.w,bv.w,acc[3][3]);
        }
        float* Pb = g_P + b * CCH * CCH;
        #pragma unroll
        for (int u = 0; u < 4; u++)
            #pragma unroll
            for (int v = 0; v < 4; v++)
                atomicAdd(&Pb[(r0 + u) * CCH + (e0 + v)], acc[u][v]);
    }
}

// ---------------- K3: out = X @ P + bp ----------------------------------------
#define ONTILE 128
#define X2S    132
#define OUT_SMEM ((CCH * X2S + CCH * CCH + CCH) * 4)

__global__ void __launch_bounds__(256, 4)
out_kernel(const float* __restrict__ x,
           const float* __restrict__ bp,
           float* __restrict__ out) {
    extern __shared__ float sm[];
    float* xs  = sm;
    float* Ps  = xs + CCH * X2S;
    float* bps = Ps + CCH * CCH;

    const int b     = blockIdx.x >> 7;
    const int chunk = blockIdx.x & 127;
    const int n0    = chunk * ONTILE;
    const int tid   = threadIdx.x;

    for (int i = tid; i < CCH * CCH; i += 256) Ps[i] = g_P[b * CCH * CCH + i];
    if (tid < CCH) bps[tid] = bp[tid];

    const float* xb = x + (size_t)b * CCH * NPIX + n0;
    for (int idx = tid; idx < CCH * (ONTILE / 4); idx += 256) {
        int row = idx >> 5, q4 = idx & 31;
        float4 v = *(const float4*)(xb + (size_t)row * NPIX + q4 * 4);
        *(float4*)(xs + row * X2S + q4 * 4) = v;
    }
    __syncthreads();

    const int tx = tid & 31;
    const int ty = tid >> 5;
    const int c0 = ty * 8;

    float acc[8][4];
    #pragma unroll
    for (int u = 0; u < 8; u++)
        #pragma unroll
        for (int v = 0; v < 4; v++) acc[u][v] = 0.f;

    #pragma unroll 4
    for (int j = 0; j < CCH; j++) {
        float4 xv = *(const float4*)(xs + j * X2S + tx * 4);
        float4 p0 = *(const float4*)(Ps + j * CCH + c0);
        float4 p1 = *(const float4*)(Ps + j * CCH + c0 + 4);
        float pu[8] = {p0.x, p0.y, p0.z, p0.w, p1.x, p1.y, p1.z, p1.w};
        #pragma unroll
        for (int u = 0; u < 8; u++) {
            acc[u][0] = fmaf(pu[u], xv.x, acc[u][0]);
            acc[u][1] = fmaf(pu[u], xv.y, acc[u][1]);
            acc[u][2] = fmaf(pu[u], xv.z, acc[u][2]);
            acc[u][3] = fmaf(pu[u], xv.w, acc[u][3]);
        }
    }

    #pragma unroll
    for (int u = 0; u < 8; u++) {
        float bias = bps[c0 + u];
        float4 o;
        o.x = acc[u][0] + bias; o.y = acc[u][1] + bias;
        o.z = acc[u][2] + bias; o.w = acc[u][3] + bias;
        *(float4*)(out + ((size_t)(b * CCH + c0 + u)) * NPIX + n0 + tx * 4) = o;
    }
}

// ---------------- launch ------------------------------------------------------
extern "C" void kernel_launch(void* const* d_in, const int* in_sizes, int n_in,
                              void* d_out, int out_size) {
    const float* x       = (const float*)d_in[0];
    const float* Wq      = (const float*)d_in[1];
    const float* Wk      = (const float*)d_in[2];
    const float* Wv      = (const float*)d_in[3];
    const float* Wp      = (const float*)d_in[4];
    const float* bp      = (const float*)d_in[5];
    const float* rescale = (const float*)d_in[6];

    float* out      = (float*)d_out;
    float* attn_out = out + (size_t)out_size - (size_t)BATCH * NHEADS * DHEAD * DHEAD;

    cudaFuncSetAttribute(gram_kernel, cudaFuncAttributeMaxDynamicSharedMemorySize, GRAM_SMEM);
    cudaFuncSetAttribute(attn_kernel, cudaFuncAttributeMaxDynamicSharedMemorySize, ATTN_SMEM);
    cudaFuncSetAttribute(out_kernel,  cudaFuncAttributeMaxDynamicSharedMemorySize, OUT_SMEM);

    zero_kernel<<<(BATCH * CCH * CCH + 255) / 256, 256>>>();
    gram_kernel<<<BATCH * 64, GRAM_THREADS, GRAM_SMEM>>>(x);
    attn_kernel<<<BATCH * NHEADS, 256, ATTN_SMEM>>>(Wq, Wk, Wv, Wp, rescale, attn_out);
    out_kernel<<<BATCH * (NPIX / ONTILE), 256, OUT_SMEM>>>(x, bp, out);
}